// round 13
// baseline (speedup 1.0000x reference)
#include <cuda_runtime.h>
#include <math.h>
#include <stdint.h>

#define KDIM     4096
#define NJ       24             // 4 pre + 4 post + 16 res
#define MM       256            // rows per CTA
#define BLOCK    256            // 8 warps, warp w owns rows w*32..w*32+31
#define KC       64             // k per chunk (256 B contiguous per row)
#define NC       (KDIM / KC)    // 64 chunks
#define XSTR     68             // floats per staged row (68 % 32 == 4 -> conflict-free)
#define STAGEF   (MM * XSTR)    // floats per stage = 17408
#define NSTG     3
#define SMEM_BYTES (NSTG * STAGEF * 4)     // 208896 B
#define SDSTR    28             // epilogue transpose stride
#define RMS_EPS  1.1920928955078125e-07f
#define SK_EPS   1e-6f

__device__ __align__(16) float g_Wt[NJ * KDIM];   // j-major, k contiguous, pre-scaled

// ---------------- helpers ----------------
__device__ __forceinline__ uint32_t smem_u32(const void* p) {
    return (uint32_t)__cvta_generic_to_shared(p);
}
__device__ __forceinline__ void cp16cg(uint32_t dst, const void* src) {
    asm volatile("cp.async.cg.shared.global [%0], [%1], 16;" :: "r"(dst), "l"(src));
}
__device__ __forceinline__ void cp_commit() { asm volatile("cp.async.commit_group;"); }
template <int N> __device__ __forceinline__ void cp_wait() {
    asm volatile("cp.async.wait_group %0;" :: "n"(N));
}
__device__ __forceinline__ void mma_tf32(float d[4],
                                         uint32_t a0, uint32_t a1, uint32_t a2, uint32_t a3,
                                         uint32_t b0, uint32_t b1) {
    asm volatile("mma.sync.aligned.m16n8k8.row.col.f32.tf32.tf32.f32 "
                 "{%0,%1,%2,%3}, {%4,%5,%6,%7}, {%8,%9}, {%0,%1,%2,%3};"
                 : "+f"(d[0]), "+f"(d[1]), "+f"(d[2]), "+f"(d[3])
                 : "r"(a0), "r"(a1), "r"(a2), "r"(a3), "r"(b0), "r"(b1));
}
__device__ __forceinline__ uint32_t f2u(float f) { return __float_as_uint(f); }

__global__ void prep_kernel(const float* __restrict__ norm_w,
                            const float* __restrict__ W_pre,
                            const float* __restrict__ W_post,
                            const float* __restrict__ W_res,
                            const float* __restrict__ a_pre,
                            const float* __restrict__ a_post,
                            const float* __restrict__ a_res) {
    int idx = blockIdx.x * blockDim.x + threadIdx.x;
    if (idx >= NJ * KDIM) return;
    int j = idx / KDIM;
    int k = idx - j * KDIM;
    float w, a;
    if (j < 4)      { w = W_pre [j * KDIM + k];       a = a_pre[0];  }
    else if (j < 8) { w = W_post[(j - 4) * KDIM + k]; a = a_post[0]; }
    else            { w = W_res [(j - 8) * KDIM + k]; a = a_res[0];  }
    g_Wt[j * KDIM + k] = w * a * norm_w[k];
}

__global__ __launch_bounds__(BLOCK, 1)
void mhc_mma_kernel(const float* __restrict__ x,
                    const float* __restrict__ b_pre,
                    const float* __restrict__ b_post,
                    const float* __restrict__ b_res,
                    float* __restrict__ out, int Btot) {
    extern __shared__ float dsm[];
    __shared__ float ssqp[BLOCK];

    const int tid  = threadIdx.x;
    const int lane = tid & 31;
    const int warp = tid >> 5;
    const int g    = lane >> 2;       // groupID
    const int c4   = lane & 3;        // threadID_in_group
    const int rowbase = blockIdx.x * MM;
    const int m0 = warp * 32;

    // ---- async chunk loader: x only (W stays in L1/L2 via __ldg) ----
    const float* xrow = x + (size_t)rowbase * KDIM;
    const uint32_t sbase = smem_u32(dsm);
    auto issue_chunk = [&](int c) {
        const int s = c % NSTG;
        const uint32_t ab = sbase + s * (STAGEF * 4);
        const float* xb = xrow + c * KC;
#pragma unroll
        for (int i = 0; i < 16; i++) {           // 4096 cp16, 16/thread
            int idx = i * BLOCK + tid;
            int r = idx >> 4, u = idx & 15;      // 16 x 16B units per 256B row piece
            cp16cg(ab + r * (XSTR * 4) + u * 16,
                   xb + (size_t)r * KDIM + u * 4);
        }
        cp_commit();
    };

    // issue distance 2 < NSTG (3): chunk c+2 never lands in chunk c's stage
    issue_chunk(0); issue_chunk(1);

    // D accumulators: [mtile][ntile][4]  (2 m16 tiles per warp, 3 n8 tiles)
    float d[2][3][4];
#pragma unroll
    for (int mt = 0; mt < 2; mt++)
#pragma unroll
        for (int n = 0; n < 3; n++)
#pragma unroll
            for (int q = 0; q < 4; q++) d[mt][n][q] = 0.0f;

    // A fragment offsets (floats, within stage)
    const int aof0 = (m0 + g) * XSTR + c4;
    const int aof1 = aof0 + 8 * XSTR;
    const int aof2 = aof0 + 16 * XSTR;
    const int aof3 = aof0 + 24 * XSTR;

    // B fragment global pointers (j-major W, L1/L2-resident)
    const float* w0 = g_Wt + (size_t)(0  + g) * KDIM + c4;
    const float* w1 = g_Wt + (size_t)(8  + g) * KDIM + c4;
    const float* w2 = g_Wt + (size_t)(16 + g) * KDIM + c4;

    float ssq = 0.0f;

    for (int c = 0; c < NC; ++c) {
        if (c + 1 < NC) cp_wait<1>(); else cp_wait<0>();
        __syncthreads();                          // chunk c resident; c-1 fully consumed
        if (c + 2 < NC) issue_chunk(c + 2);       // stage (c+2)%3 == (c-1)%3 (consumed)

        const float* fs = dsm + (c % NSTG) * STAGEF;
        const int kg = c * KC;

        // ssq: thread owns row tid (exact fp32), 16 float4
        {
            const float4* xr = (const float4*)(fs + tid * XSTR);
#pragma unroll
            for (int i = 0; i < 16; i++) {
                float4 v = xr[i];
                ssq += v.x * v.x + v.y * v.y + v.z * v.z + v.w * v.w;
            }
        }

        // MMA: 8 k8-steps, 2 m-tiles x 3 n-tiles
#pragma unroll
        for (int ks = 0; ks < 8; ks++) {
            const int k0 = ks * 8;
            uint32_t A0[4], A1[4];
            A0[0] = f2u(fs[aof0 + k0]);     A0[1] = f2u(fs[aof1 + k0]);
            A0[2] = f2u(fs[aof0 + k0 + 4]); A0[3] = f2u(fs[aof1 + k0 + 4]);
            A1[0] = f2u(fs[aof2 + k0]);     A1[1] = f2u(fs[aof3 + k0]);
            A1[2] = f2u(fs[aof2 + k0 + 4]); A1[3] = f2u(fs[aof3 + k0 + 4]);
            uint32_t b0, b1;
            b0 = f2u(__ldg(w0 + kg + k0)); b1 = f2u(__ldg(w0 + kg + k0 + 4));
            mma_tf32(d[0][0], A0[0], A0[1], A0[2], A0[3], b0, b1);
            mma_tf32(d[1][0], A1[0], A1[1], A1[2], A1[3], b0, b1);
            b0 = f2u(__ldg(w1 + kg + k0)); b1 = f2u(__ldg(w1 + kg + k0 + 4));
            mma_tf32(d[0][1], A0[0], A0[1], A0[2], A0[3], b0, b1);
            mma_tf32(d[1][1], A1[0], A1[1], A1[2], A1[3], b0, b1);
            b0 = f2u(__ldg(w2 + kg + k0)); b1 = f2u(__ldg(w2 + kg + k0 + 4));
            mma_tf32(d[0][2], A0[0], A0[1], A0[2], A0[3], b0, b1);
            mma_tf32(d[1][2], A1[0], A1[1], A1[2], A1[3], b0, b1);
        }
    }

    ssqp[tid] = ssq;                              // tid == row
    __syncthreads();                              // reuse dsm for sD

    // transpose D through smem: sD[row][j], stride 28
    float* sD = dsm;
#pragma unroll
    for (int mt = 0; mt < 2; mt++) {
        const int r0 = m0 + mt * 16 + g;
#pragma unroll
        for (int n = 0; n < 3; n++) {
            *(float2*)&sD[r0 * SDSTR + 8 * n + 2 * c4] =
                make_float2(d[mt][n][0], d[mt][n][1]);
            *(float2*)&sD[(r0 + 8) * SDSTR + 8 * n + 2 * c4] =
                make_float2(d[mt][n][2], d[mt][n][3]);
        }
    }
    __syncthreads();

    // epilogue: one row per thread
    {
        const int row = rowbase + tid;
        const float* a = &sD[tid * SDSTR];
        const float rinv = rsqrtf(ssqp[tid] * (1.0f / (float)KDIM) + RMS_EPS);

        float4 o;
        {
            float p0 = rinv * a[0] + b_pre[0];
            float p1 = rinv * a[1] + b_pre[1];
            float p2 = rinv * a[2] + b_pre[2];
            float p3 = rinv * a[3] + b_pre[3];
            o.x = __fdividef(1.0f, 1.0f + __expf(-p0));
            o.y = __fdividef(1.0f, 1.0f + __expf(-p1));
            o.z = __fdividef(1.0f, 1.0f + __expf(-p2));
            o.w = __fdividef(1.0f, 1.0f + __expf(-p3));
            *(float4*)(out + (size_t)row * 4) = o;
        }
        {
            float p0 = rinv * a[4] + b_post[0];
            float p1 = rinv * a[5] + b_post[1];
            float p2 = rinv * a[6] + b_post[2];
            float p3 = rinv * a[7] + b_post[3];
            o.x = 2.0f * __fdividef(1.0f, 1.0f + __expf(-p0));
            o.y = 2.0f * __fdividef(1.0f, 1.0f + __expf(-p1));
            o.z = 2.0f * __fdividef(1.0f, 1.0f + __expf(-p2));
            o.w = 2.0f * __fdividef(1.0f, 1.0f + __expf(-p3));
            *(float4*)(out + (size_t)Btot * 4 + (size_t)row * 4) = o;
        }

        float M[16];
#pragma unroll
        for (int j = 0; j < 16; j++)
            M[j] = __expf(rinv * a[8 + j] + b_res[j]);
#pragma unroll 1
        for (int it = 0; it < 20; it++) {
#pragma unroll
            for (int r = 0; r < 4; r++) {
                float sv = M[4*r] + M[4*r+1] + M[4*r+2] + M[4*r+3] + SK_EPS;
                float inv = __fdividef(1.0f, sv);
                M[4*r] *= inv; M[4*r+1] *= inv; M[4*r+2] *= inv; M[4*r+3] *= inv;
            }
#pragma unroll
            for (int cq = 0; cq < 4; cq++) {
                float sv = M[cq] + M[cq+4] + M[cq+8] + M[cq+12] + SK_EPS;
                float inv = __fdividef(1.0f, sv);
                M[cq] *= inv; M[cq+4] *= inv; M[cq+8] *= inv; M[cq+12] *= inv;
            }
        }
        float* ro = out + (size_t)Btot * 8 + (size_t)row * 16;
#pragma unroll
        for (int q = 0; q < 4; q++) {
            o.x = M[4*q]; o.y = M[4*q+1]; o.z = M[4*q+2]; o.w = M[4*q+3];
            *(float4*)(ro + 4 * q) = o;
        }
    }
}

extern "C" void kernel_launch(void* const* d_in, const int* in_sizes, int n_in,
                              void* d_out, int out_size) {
    const float* x      = (const float*)d_in[0];
    const float* norm_w = (const float*)d_in[1];
    const float* W_pre  = (const float*)d_in[2];
    const float* W_post = (const float*)d_in[3];
    const float* W_res  = (const float*)d_in[4];
    const float* b_pre  = (const float*)d_in[5];
    const float* b_post = (const float*)d_in[6];
    const float* b_res  = (const float*)d_in[7];
    const float* a_pre  = (const float*)d_in[8];
    const float* a_post = (const float*)d_in[9];
    const float* a_res  = (const float*)d_in[10];

    const int Btot = in_sizes[0] / KDIM;

    cudaFuncSetAttribute(mhc_mma_kernel,
                         cudaFuncAttributeMaxDynamicSharedMemorySize,
                         SMEM_BYTES);

    prep_kernel<<<(NJ * KDIM + 255) / 256, 256>>>(norm_w, W_pre, W_post, W_res,
                                                  a_pre, a_post, a_res);
    mhc_mma_kernel<<<Btot / MM, BLOCK, SMEM_BYTES>>>(x, b_pre, b_post, b_res,
                                                     (float*)d_out, Btot);
}

// round 14
// speedup vs baseline: 2.4609x; 2.4609x over previous
#include <cuda_runtime.h>
#include <math.h>
#include <stdint.h>

#define KDIM     4096
#define NJ       24             // 4 pre + 4 post + 16 res
#define MM       256            // rows per CTA
#define BLOCK    256            // 8 warps, warp w owns rows w*32..w*32+31
#define KC       64             // k per chunk (256 B contiguous per row)
#define NC       (KDIM / KC)    // 64 chunks
#define NSTG     3
#define XW_OFF   65536          // byte offset of W tile inside a stage (x = 256*256B)
#define STAGE_BYTES (XW_OFF + NJ * 256)     // 71680
#define SMEM_BYTES  (NSTG * STAGE_BYTES)    // 215040
#define SDSTR    28             // epilogue transpose stride
#define RMS_EPS  1.1920928955078125e-07f
#define SK_EPS   1e-6f

__device__ __align__(16) float g_Wt[NJ * KDIM];   // j-major, k contiguous, pre-scaled

// ---------------- helpers ----------------
__device__ __forceinline__ uint32_t smem_u32(const void* p) {
    return (uint32_t)__cvta_generic_to_shared(p);
}
__device__ __forceinline__ void cp16cg(uint32_t dst, const void* src) {
    asm volatile("cp.async.cg.shared.global [%0], [%1], 16;" :: "r"(dst), "l"(src));
}
__device__ __forceinline__ void cp16ca(uint32_t dst, const void* src) {
    asm volatile("cp.async.ca.shared.global [%0], [%1], 16;" :: "r"(dst), "l"(src));
}
__device__ __forceinline__ void cp_commit() { asm volatile("cp.async.commit_group;"); }
template <int N> __device__ __forceinline__ void cp_wait() {
    asm volatile("cp.async.wait_group %0;" :: "n"(N));
}
__device__ __forceinline__ void mma_tf32(float d[4],
                                         uint32_t a0, uint32_t a1, uint32_t a2, uint32_t a3,
                                         uint32_t b0, uint32_t b1) {
    asm volatile("mma.sync.aligned.m16n8k8.row.col.f32.tf32.tf32.f32 "
                 "{%0,%1,%2,%3}, {%4,%5,%6,%7}, {%8,%9}, {%0,%1,%2,%3};"
                 : "+f"(d[0]), "+f"(d[1]), "+f"(d[2]), "+f"(d[3])
                 : "r"(a0), "r"(a1), "r"(a2), "r"(a3), "r"(b0), "r"(b1));
}
__device__ __forceinline__ uint32_t f2u(float f) { return __float_as_uint(f); }

__global__ void prep_kernel(const float* __restrict__ norm_w,
                            const float* __restrict__ W_pre,
                            const float* __restrict__ W_post,
                            const float* __restrict__ W_res,
                            const float* __restrict__ a_pre,
                            const float* __restrict__ a_post,
                            const float* __restrict__ a_res) {
    int idx = blockIdx.x * blockDim.x + threadIdx.x;
    if (idx >= NJ * KDIM) return;
    int j = idx / KDIM;
    int k = idx - j * KDIM;
    float w, a;
    if (j < 4)      { w = W_pre [j * KDIM + k];       a = a_pre[0];  }
    else if (j < 8) { w = W_post[(j - 4) * KDIM + k]; a = a_post[0]; }
    else            { w = W_res [(j - 8) * KDIM + k]; a = a_res[0];  }
    g_Wt[j * KDIM + k] = w * a * norm_w[k];
}

__global__ __launch_bounds__(BLOCK, 1)
void mhc_mma_kernel(const float* __restrict__ x,
                    const float* __restrict__ b_pre,
                    const float* __restrict__ b_post,
                    const float* __restrict__ b_res,
                    float* __restrict__ out, int Btot) {
    extern __shared__ float dsm[];
    __shared__ float ssqp[BLOCK];

    const int tid  = threadIdx.x;
    const int lane = tid & 31;
    const int warp = tid >> 5;
    const int g    = lane >> 2;       // groupID
    const int c4   = lane & 3;        // threadID_in_group
    const int rowbase = blockIdx.x * MM;
    const int m0 = warp * 32;

    // ---- async chunk loader: rows packed at 256 B, 16B-unit XOR swizzle (u ^= row&15)
    const float* xrow = x + (size_t)rowbase * KDIM;
    const uint32_t sbase = smem_u32(dsm);
    auto issue_chunk = [&](int c) {
        const int s = c % NSTG;
        const uint32_t ab = sbase + s * STAGE_BYTES;
        const float* xb = xrow + c * KC;
#pragma unroll
        for (int i = 0; i < 16; i++) {           // 4096 x-units, 16/thread
            int idx = i * BLOCK + tid;
            int r = idx >> 4, u = idx & 15;
            cp16cg(ab + r * 256 + ((u ^ (r & 15)) << 4),
                   xb + (size_t)r * KDIM + u * 4);
        }
#pragma unroll
        for (int idx = tid; idx < NJ * 16; idx += BLOCK) {   // 384 W-units
            int j = idx >> 4, u = idx & 15;
            cp16ca(ab + XW_OFF + j * 256 + ((u ^ (j & 15)) << 4),
                   g_Wt + (size_t)j * KDIM + c * KC + u * 4);
        }
        cp_commit();
    };

    // issue distance 2 < NSTG(3): chunk c+2 lands in stage (c-1)%3, already consumed
    issue_chunk(0); issue_chunk(1);

    // D accumulators: [mtile][ntile][4]  (2 m16 tiles per warp, 3 n8 tiles)
    float d[2][3][4];
#pragma unroll
    for (int mt = 0; mt < 2; mt++)
#pragma unroll
        for (int n = 0; n < 3; n++)
#pragma unroll
            for (int q = 0; q < 4; q++) d[mt][n][q] = 0.0f;

    // row bases (floats, within stage); swizzle keys: rows m0+g,m0+16+g -> g; +8/+24 -> g^8
    const int ra0 = (m0 + g) * 64 + c4;
    const int ra1 = (m0 + 8 + g) * 64 + c4;
    const int ra2 = (m0 + 16 + g) * 64 + c4;
    const int ra3 = (m0 + 24 + g) * 64 + c4;
    const int XWf = XW_OFF / 4;
    const int bw0 = XWf + g * 64 + c4;            // key g
    const int bw1 = XWf + (8 + g) * 64 + c4;      // key g^8
    const int bw2 = XWf + (16 + g) * 64 + c4;     // key g

    const int skey = tid & 15;                    // ssq swizzle key (row = tid)
    const int srow = tid * 64;

    float ssq = 0.0f;

    for (int c = 0; c < NC; ++c) {
        if (c + 1 < NC) cp_wait<1>(); else cp_wait<0>();
        __syncthreads();                          // chunk c resident; c-1 fully consumed
        if (c + 2 < NC) issue_chunk(c + 2);

        const float* fs = dsm + (c % NSTG) * (STAGE_BYTES / 4);

        // ssq: thread owns row tid (exact fp32), 16 swizzled float4
#pragma unroll
        for (int i = 0; i < 16; i++) {
            float4 v = *(const float4*)(fs + srow + ((i ^ skey) << 2));
            ssq += v.x * v.x + v.y * v.y + v.z * v.z + v.w * v.w;
        }

        // MMA: 8 k8-steps, 2 m-tiles x 3 n-tiles
#pragma unroll
        for (int ks = 0; ks < 8; ks++) {
            const int u0 = ((2 * ks)     ^ g) << 2;   // float offset, key g
            const int u1 = ((2 * ks + 1) ^ g) << 2;
            const int u0x = u0 ^ 32;                  // key g^8
            const int u1x = u1 ^ 32;
            uint32_t A0[4], A1[4];
            A0[0] = f2u(fs[ra0 + u0]);  A0[1] = f2u(fs[ra1 + u0x]);
            A0[2] = f2u(fs[ra0 + u1]);  A0[3] = f2u(fs[ra1 + u1x]);
            A1[0] = f2u(fs[ra2 + u0]);  A1[1] = f2u(fs[ra3 + u0x]);
            A1[2] = f2u(fs[ra2 + u1]);  A1[3] = f2u(fs[ra3 + u1x]);
            uint32_t b0, b1;
            b0 = f2u(fs[bw0 + u0]);  b1 = f2u(fs[bw0 + u1]);
            mma_tf32(d[0][0], A0[0], A0[1], A0[2], A0[3], b0, b1);
            mma_tf32(d[1][0], A1[0], A1[1], A1[2], A1[3], b0, b1);
            b0 = f2u(fs[bw1 + u0x]); b1 = f2u(fs[bw1 + u1x]);
            mma_tf32(d[0][1], A0[0], A0[1], A0[2], A0[3], b0, b1);
            mma_tf32(d[1][1], A1[0], A1[1], A1[2], A1[3], b0, b1);
            b0 = f2u(fs[bw2 + u0]);  b1 = f2u(fs[bw2 + u1]);
            mma_tf32(d[0][2], A0[0], A0[1], A0[2], A0[3], b0, b1);
            mma_tf32(d[1][2], A1[0], A1[1], A1[2], A1[3], b0, b1);
        }
    }

    ssqp[tid] = ssq;                              // tid == row
    __syncthreads();                              // reuse dsm for sD

    // transpose D through smem: sD[row][j], stride 28
    float* sD = dsm;
#pragma unroll
    for (int mt = 0; mt < 2; mt++) {
        const int r0 = m0 + mt * 16 + g;
#pragma unroll
        for (int n = 0; n < 3; n++) {
            *(float2*)&sD[r0 * SDSTR + 8 * n + 2 * c4] =
                make_float2(d[mt][n][0], d[mt][n][1]);
            *(float2*)&sD[(r0 + 8) * SDSTR + 8 * n + 2 * c4] =
                make_float2(d[mt][n][2], d[mt][n][3]);
        }
    }
    __syncthreads();

    // epilogue: one row per thread
    {
        const int row = rowbase + tid;
        const float* a = &sD[tid * SDSTR];
        const float rinv = rsqrtf(ssqp[tid] * (1.0f / (float)KDIM) + RMS_EPS);

        float4 o;
        {
            float p0 = rinv * a[0] + b_pre[0];
            float p1 = rinv * a[1] + b_pre[1];
            float p2 = rinv * a[2] + b_pre[2];
            float p3 = rinv * a[3] + b_pre[3];
            o.x = __fdividef(1.0f, 1.0f + __expf(-p0));
            o.y = __fdividef(1.0f, 1.0f + __expf(-p1));
            o.z = __fdividef(1.0f, 1.0f + __expf(-p2));
            o.w = __fdividef(1.0f, 1.0f + __expf(-p3));
            *(float4*)(out + (size_t)row * 4) = o;
        }
        {
            float p0 = rinv * a[4] + b_post[0];
            float p1 = rinv * a[5] + b_post[1];
            float p2 = rinv * a[6] + b_post[2];
            float p3 = rinv * a[7] + b_post[3];
            o.x = 2.0f * __fdividef(1.0f, 1.0f + __expf(-p0));
            o.y = 2.0f * __fdividef(1.0f, 1.0f + __expf(-p1));
            o.z = 2.0f * __fdividef(1.0f, 1.0f + __expf(-p2));
            o.w = 2.0f * __fdividef(1.0f, 1.0f + __expf(-p3));
            *(float4*)(out + (size_t)Btot * 4 + (size_t)row * 4) = o;
        }

        float M[16];
#pragma unroll
        for (int j = 0; j < 16; j++)
            M[j] = __expf(rinv * a[8 + j] + b_res[j]);
#pragma unroll 1
        for (int it = 0; it < 20; it++) {
#pragma unroll
            for (int r = 0; r < 4; r++) {
                float sv = M[4*r] + M[4*r+1] + M[4*r+2] + M[4*r+3] + SK_EPS;
                float inv = __fdividef(1.0f, sv);
                M[4*r] *= inv; M[4*r+1] *= inv; M[4*r+2] *= inv; M[4*r+3] *= inv;
            }
#pragma unroll
            for (int cq = 0; cq < 4; cq++) {
                float sv = M[cq] + M[cq+4] + M[cq+8] + M[cq+12] + SK_EPS;
                float inv = __fdividef(1.0f, sv);
                M[cq] *= inv; M[cq+4] *= inv; M[cq+8] *= inv; M[cq+12] *= inv;
            }
        }
        float* ro = out + (size_t)Btot * 8 + (size_t)row * 16;
#pragma unroll
        for (int q = 0; q < 4; q++) {
            o.x = M[4*q]; o.y = M[4*q+1]; o.z = M[4*q+2]; o.w = M[4*q+3];
            *(float4*)(ro + 4 * q) = o;
        }
    }
}

extern "C" void kernel_launch(void* const* d_in, const int* in_sizes, int n_in,
                              void* d_out, int out_size) {
    const float* x      = (const float*)d_in[0];
    const float* norm_w = (const float*)d_in[1];
    const float* W_pre  = (const float*)d_in[2];
    const float* W_post = (const float*)d_in[3];
    const float* W_res  = (const float*)d_in[4];
    const float* b_pre  = (const float*)d_in[5];
    const float* b_post = (const float*)d_in[6];
    const float* b_res  = (const float*)d_in[7];
    const float* a_pre  = (const float*)d_in[8];
    const float* a_post = (const float*)d_in[9];
    const float* a_res  = (const float*)d_in[10];

    const int Btot = in_sizes[0] / KDIM;

    cudaFuncSetAttribute(mhc_mma_kernel,
                         cudaFuncAttributeMaxDynamicSharedMemorySize,
                         SMEM_BYTES);

    prep_kernel<<<(NJ * KDIM + 255) / 256, 256>>>(norm_w, W_pre, W_post, W_res,
                                                  a_pre, a_post, a_res);
    mhc_mma_kernel<<<Btot / MM, BLOCK, SMEM_BYTES>>>(x, b_pre, b_post, b_res,
                                                     (float*)d_out, Btot);
}